// round 1
// baseline (speedup 1.0000x reference)
#include <cuda_runtime.h>

// Problem constants (fixed by reference): H=64, M=N=128, k=9, w=3
#define HZ   64
#define NYD  128
#define NXD  128
#define PTOT (HZ * NYD * NXD)   // 1,048,576 voxels
#define KNN  9

// Scratch: packed top-9 neighbor codes, 6 bits each (window position 0..26).
__device__ unsigned long long g_code[PTOT];

// ---------------------------------------------------------------------------
// Pass 1: per voxel, stable-select the 9 value-closest of 27 periodic
// neighbors; pack their window-position codes (6 bits each) into a uint64.
// Rank formula encodes jnp.argsort(stable) tie-break (lower column index wins):
//   rank(c) = #{ j<c : d[j] <= d[c] } + #{ j>c : d[j] < d[c] }
// Fully unrolled -> all arrays live in registers.
// ---------------------------------------------------------------------------
__global__ __launch_bounds__(256) void pass1_kernel(const float* __restrict__ anat) {
    int i = blockIdx.x * 256 + threadIdx.x;
    int x = i & 127;
    int y = (i >> 7) & 127;
    int z = i >> 14;

    int zo[3] = { ((z + 63) & 63) << 14, z << 14, ((z + 1) & 63) << 14 };
    int yo[3] = { ((y + 127) & 127) << 7, y << 7, ((y + 1) & 127) << 7 };
    int xo[3] = { (x + 127) & 127, x, (x + 1) & 127 };

    float ac = __ldg(&anat[i]);
    float d[27];
#pragma unroll
    for (int oz = 0; oz < 3; ++oz)
#pragma unroll
        for (int oy = 0; oy < 3; ++oy)
#pragma unroll
            for (int ox = 0; ox < 3; ++ox) {
                int c = oz * 9 + oy * 3 + ox;
                float v = __ldg(&anat[zo[oz] + yo[oy] + xo[ox]]);
                d[c] = fabsf(v - ac);
            }

    unsigned long long codeacc = 0ULL;
#pragma unroll
    for (int c = 0; c < 27; ++c) {
        int r = 0;
#pragma unroll
        for (int j = 0; j < 27; ++j) {
            if (j == c) continue;
            if (j < c) r += (d[j] <= d[c]);
            else       r += (d[j] <  d[c]);
        }
        if (r < KNN)
            codeacc |= ((unsigned long long)c) << (6 * r);
    }
    g_code[i] = codeacc;
}

// Decode window-position code c (0..26) relative to voxel (z,y,x) -> flat id.
__device__ __forceinline__ int decode_id(int c, int z, int y, int x) {
    int oz = c / 9;
    int rem = c - 9 * oz;
    int oy = rem / 3;
    int ox = rem - 3 * oy;
    int zn = (z + oz + 63) & 63;     // oz in {0,1,2} represents offset oz-1
    int yn = (y + oy + 127) & 127;
    int xn = (x + ox + 127) & 127;
    return (zn << 14) | (yn << 7) | xn;
}

// ---------------------------------------------------------------------------
// Pass 2: per voxel, reconstruct own Wk (9 gathers) and each selected
// neighbor's Wk (81 gathers, all L1/L2-resident), compute sigma (ddof=1,
// two-pass for fp32 stability), squared patch distances, softmax.
// ---------------------------------------------------------------------------
__global__ __launch_bounds__(256) void pass2_kernel(const float* __restrict__ anat,
                                                    const float* __restrict__ ksig,
                                                    float* __restrict__ out) {
    int i = blockIdx.x * 256 + threadIdx.x;
    int x = i & 127;
    int y = (i >> 7) & 127;
    int z = i >> 14;

    unsigned long long ci = g_code[i];
    float wi[KNN];
    int   nid[KNN];
#pragma unroll
    for (int j = 0; j < KNN; ++j) {
        int c = (int)((ci >> (6 * j)) & 63);
        nid[j] = decode_id(c, z, y, x);
        wi[j] = __ldg(&anat[nid[j]]);
    }

    // sigma = std(Wk, ddof=1), two-pass to avoid cancellation
    float sum = 0.f;
#pragma unroll
    for (int j = 0; j < KNN; ++j) sum += wi[j];
    float mean = sum * (1.0f / 9.0f);
    float var = 0.f;
#pragma unroll
    for (int j = 0; j < KNN; ++j) { float t = wi[j] - mean; var += t * t; }
    var *= (1.0f / 8.0f);
    float sigma = sqrtf(var);
    bool  zeroSig = (sigma == 0.0f);
    float sig = zeroSig ? 1.0f : sigma;

    float ks  = __ldg(&ksig[0]);
    // logits = -(norm / sigma / (sqrt(2)*ks))^2 = -s / (2 * sigma^2 * ks^2)
    float inv = 1.0f / (2.0f * sig * sig * ks * ks);

    float logits[KNN];
#pragma unroll
    for (int j = 0; j < KNN; ++j) {
        int nj = nid[j];
        int xj = nj & 127;
        int yj = (nj >> 7) & 127;
        int zj = nj >> 14;
        unsigned long long cn = __ldg(&g_code[nj]);
        float s = 0.f;
#pragma unroll
        for (int t = 0; t < KNN; ++t) {
            int c = (int)((cn >> (6 * t)) & 63);
            float wn = __ldg(&anat[decode_id(c, zj, yj, xj)]);
            float df = wi[t] - wn + 1e-6f;
            s += df * df;
        }
        logits[j] = zeroSig ? 0.0f : -(s * inv);
    }

    // softmax over the 9 neighbors
    float mx = logits[0];
#pragma unroll
    for (int j = 1; j < KNN; ++j) mx = fmaxf(mx, logits[j]);
    float e[KNN], se = 0.f;
#pragma unroll
    for (int j = 0; j < KNN; ++j) { e[j] = __expf(logits[j] - mx); se += e[j]; }
    float rse = 1.0f / se;
#pragma unroll
    for (int j = 0; j < KNN; ++j) out[i * KNN + j] = e[j] * rse;
}

extern "C" void kernel_launch(void* const* d_in, const int* in_sizes, int n_in,
                              void* d_out, int out_size) {
    const float* anat = (const float*)d_in[0];
    const float* ksig = (const float*)d_in[1];
    float* out = (float*)d_out;

    const int blocks = PTOT / 256;
    pass1_kernel<<<blocks, 256>>>(anat);
    pass2_kernel<<<blocks, 256>>>(anat, ksig, out);
}

// round 2
// speedup vs baseline: 1.1474x; 1.1474x over previous
#include <cuda_runtime.h>

// Problem constants: H=64, M=N=128, k=9, w=3
#define HZ   64
#define NYD  128
#define NXD  128
#define PTOT (HZ * NYD * NXD)   // 1,048,576 voxels
#define KNN  9
#define ROWW 12                 // padded row width (floats) -> 48B, float4-aligned

// Scratch (static __device__ arrays are the allowed scratch mechanism)
__device__ float g_val[PTOT * ROWW];            // 50.3 MB: 9 selected values per voxel, rank-ordered
__device__ unsigned long long g_code[PTOT];     // 8 MB: 9 window codes (6b each), rank-ordered

// ---------------------------------------------------------------------------
// Pass 1: stable top-9 selection of 27 periodic neighbors by |v - center|.
// Rank of candidate c:  r(c) = #{j<c : d[j] <= d[c]} + #{j>c : d[j] < d[c]}
// computed with ONE compare per unordered pair:
//   pair (j<c): p = d[j] <= d[c]  ->  r_c += p ; r_j += !p
// Pipe balancing: alternate pairs between integer compares on abs-bit patterns
// (ALU pipe; monotone since d >= 0) and float compares (FMA pipe).
// Rank accumulators are packed: int side = 4 byte-counters per reg,
// float side = 2 counters per reg (weights 1.0 / 1024.0; exact in fp32).
// ---------------------------------------------------------------------------
__global__ __launch_bounds__(256) void pass1_kernel(const float* __restrict__ anat) {
    int i = blockIdx.x * 256 + threadIdx.x;
    int x = i & 127;
    int y = (i >> 7) & 127;
    int z = i >> 14;

    int zo[3] = { ((z + 63) & 63) << 14, z << 14, ((z + 1) & 63) << 14 };
    int yo[3] = { ((y + 127) & 127) << 7, y << 7, ((y + 1) & 127) << 7 };
    int xo[3] = { (x + 127) & 127, x, (x + 1) & 127 };

    float ac = __ldg(&anat[i]);
    float dv[27];                       // signed difference (value recoverable: v = ac + dv)
#pragma unroll
    for (int oz = 0; oz < 3; ++oz)
#pragma unroll
        for (int oy = 0; oy < 3; ++oy)
#pragma unroll
            for (int ox = 0; ox < 3; ++ox) {
                int c = oz * 9 + oy * 3 + ox;
                dv[c] = __ldg(&anat[zo[oz] + yo[oy] + xo[ox]]) - ac;
            }

    int di[27];                         // abs-bit patterns: int order == float order for d>=0
#pragma unroll
    for (int c = 0; c < 27; ++c) di[c] = __float_as_int(dv[c]) & 0x7fffffff;

    float rfp[14];
    int   rip[7];
#pragma unroll
    for (int k = 0; k < 14; ++k) rfp[k] = 0.0f;
#pragma unroll
    for (int k = 0; k < 7;  ++k) rip[k] = 0;

#pragma unroll
    for (int c = 1; c < 27; ++c) {
#pragma unroll
        for (int j = 0; j < c; ++j) {
            if (((c + j) & 1) == 0) {
                // float path (FMA pipe)
                bool p = fabsf(dv[j]) <= fabsf(dv[c]);
                rfp[c >> 1] += p ? ((c & 1) ? 1024.0f : 1.0f) : 0.0f;
                rfp[j >> 1] += p ? 0.0f : ((j & 1) ? 1024.0f : 1.0f);
            } else {
                // int path (ALU pipe)
                bool p = di[j] <= di[c];
                rip[c >> 2] += p ? (1 << ((c & 3) * 8)) : 0;
                rip[j >> 2] += p ? 0 : (1 << ((j & 3) * 8));
            }
        }
    }

    int rfi[14];
#pragma unroll
    for (int k = 0; k < 14; ++k) rfi[k] = (int)rfp[k];

    unsigned long long code = 0ULL;
    float* myrow = &g_val[i * ROWW];
#pragma unroll
    for (int c = 0; c < 27; ++c) {
        int r = ((rip[c >> 2] >> ((c & 3) * 8)) & 255)
              + ((c & 1) ? (rfi[c >> 1] >> 10) : (rfi[c >> 1] & 1023));
        if (r < KNN) {
            code |= ((unsigned long long)c) << (6 * r);
            myrow[r] = ac + dv[c];
        }
    }
    g_code[i] = code;
}

// Decode window-position code c (0..26) relative to voxel (z,y,x) -> flat id.
__device__ __forceinline__ int decode_id(int c, int z, int y, int x) {
    int oz = c / 9;
    int rem = c - 9 * oz;
    int oy = rem / 3;
    int ox = rem - 3 * oy;
    int zn = (z + oz + 63) & 63;
    int yn = (y + oy + 127) & 127;
    int xn = (x + ox + 127) & 127;
    return (zn << 14) | (yn << 7) | xn;
}

// ---------------------------------------------------------------------------
// Pass 2: all Wk rows come prematerialized from g_val (no per-neighbor decode
// of their selections, no anat gathers). 1 LDG.64 + 30 LDG.128 per voxel.
// Output staged through shared memory for coalesced stores.
// ---------------------------------------------------------------------------
__global__ __launch_bounds__(256) void pass2_kernel(const float* __restrict__ ksig,
                                                    float* __restrict__ out) {
    int tid = threadIdx.x;
    int i = blockIdx.x * 256 + tid;
    int x = i & 127;
    int y = (i >> 7) & 127;
    int z = i >> 14;

    unsigned long long ci = g_code[i];

    const float4* myrow4 = (const float4*)&g_val[i * ROWW];
    float4 a0 = __ldg(&myrow4[0]);
    float4 a1 = __ldg(&myrow4[1]);
    float4 a2 = __ldg(&myrow4[2]);
    float wi[KNN] = { a0.x, a0.y, a0.z, a0.w, a1.x, a1.y, a1.z, a1.w, a2.x };

    // sigma = std(Wk, ddof=1), two-pass for fp32 stability
    float sum = 0.f;
#pragma unroll
    for (int t = 0; t < KNN; ++t) sum += wi[t];
    float mean = sum * (1.0f / 9.0f);
    float var = 0.f;
#pragma unroll
    for (int t = 0; t < KNN; ++t) { float d = wi[t] - mean; var += d * d; }
    var *= (1.0f / 8.0f);
    float sigma = sqrtf(var);
    bool  zeroSig = (sigma == 0.0f);
    float sig = zeroSig ? 1.0f : sigma;

    float ks = __ldg(&ksig[0]);
    // logits = -(||diff|| / sigma / (sqrt(2)*ks))^2 = -s / (2*sigma^2*ks^2)
    float inv = 1.0f / (2.0f * sig * sig * ks * ks);

    float wie[KNN];
#pragma unroll
    for (int t = 0; t < KNN; ++t) wie[t] = wi[t] + 1e-6f;

    float logits[KNN];
#pragma unroll
    for (int j = 0; j < KNN; ++j) {
        int c = (int)((ci >> (6 * j)) & 63);
        int nj = decode_id(c, z, y, x);
        const float4* nr = (const float4*)&g_val[nj * ROWW];
        float4 b0 = __ldg(&nr[0]);
        float4 b1 = __ldg(&nr[1]);
        float4 b2 = __ldg(&nr[2]);
        float wn[KNN] = { b0.x, b0.y, b0.z, b0.w, b1.x, b1.y, b1.z, b1.w, b2.x };
        float s = 0.f;
#pragma unroll
        for (int t = 0; t < KNN; ++t) {
            float df = wie[t] - wn[t];
            s = fmaf(df, df, s);
        }
        logits[j] = zeroSig ? 0.0f : -(s * inv);
    }

    // softmax over the 9 neighbors
    float mx = logits[0];
#pragma unroll
    for (int j = 1; j < KNN; ++j) mx = fmaxf(mx, logits[j]);
    float e[KNN], se = 0.f;
#pragma unroll
    for (int j = 0; j < KNN; ++j) { e[j] = __expf(logits[j] - mx); se += e[j]; }
    float rse = 1.0f / se;

    // coalesced output via shared-memory transpose (stride 9 is conflict-free)
    __shared__ float so[256 * KNN];
#pragma unroll
    for (int j = 0; j < KNN; ++j) so[tid * KNN + j] = e[j] * rse;
    __syncthreads();
    int base = blockIdx.x * (256 * KNN);
#pragma unroll
    for (int t = 0; t < KNN; ++t)
        out[base + t * 256 + tid] = so[t * 256 + tid];
}

extern "C" void kernel_launch(void* const* d_in, const int* in_sizes, int n_in,
                              void* d_out, int out_size) {
    const float* anat = (const float*)d_in[0];
    const float* ksig = (const float*)d_in[1];
    float* out = (float*)d_out;

    const int blocks = PTOT / 256;
    pass1_kernel<<<blocks, 256>>>(anat);
    pass2_kernel<<<blocks, 256>>>(ksig, out);
}

// round 3
// speedup vs baseline: 1.1742x; 1.0234x over previous
#include <cuda_runtime.h>

// Problem constants: H=64, M=N=128, k=9, w=3
#define PTOT (64 * 128 * 128)
#define KNN  9

// Tile: 16 x 4 x 4 voxels per block; halo 18 x 6 x 6
#define TX 16
#define TY 4
#define TZ 4
#define HX 18
#define HY 6
#define HZH 6
#define HROWS (HX * HY * HZH)   // 648
#define HXY (HX * HY)           // 108

// Scratch: per-voxel 9 selected values (12-float padded row, as 3 float4)
// and 9 window codes (bytes packed in 3 u32 words).
__device__ float4       g_val4[PTOT * 3];    // 50.3 MB
__device__ unsigned int g_code32[PTOT * 3];  // 12.6 MB

// ---------------------------------------------------------------------------
// Pass 1: stable top-9 selection of the 27 periodic window neighbors by
// |v - center|.  rank(c) = #{j<c: d_j <= d_c} + #{j>c: d_j < d_c}, one compare
// per unordered pair; pairs alternate between int compares (bit pattern of the
// non-negative float — same ordering, ALU pipe) and float compares (FMA pipe)
// ON THE SAME REGISTERS. Packed rank accumulators: 4 byte-counters per int reg,
// 2 counters per float reg (weights 1 / 1024, exact in fp32).
// Values/codes scatter-staged in smem, written out coalesced.
// ---------------------------------------------------------------------------
__global__ __launch_bounds__(256) void pass1_kernel(const float* __restrict__ anat) {
    __shared__ float        s_anat[HROWS];
    __shared__ float4       s_val[256 * 3];
    __shared__ unsigned int s_code[256 * 3];

    int tid = threadIdx.x;
    int lx = tid & 15, ly = (tid >> 4) & 3, lz = tid >> 6;
    int x0 = blockIdx.x * TX, y0 = blockIdx.y * TY, z0 = blockIdx.z * TZ;

    for (int t = tid; t < HROWS; t += 256) {
        int hx = t % HX; int r = t / HX; int hy = r % HY; int hz = r / HY;
        int gx = (x0 + hx + 127) & 127;
        int gy = (y0 + hy + 127) & 127;
        int gz = (z0 + hz + 63) & 63;
        s_anat[t] = __ldg(&anat[(gz << 14) | (gy << 7) | gx]);
    }
    __syncthreads();

    int center = (lz + 1) * HXY + (ly + 1) * HX + (lx + 1);
    float ac = s_anat[center];

    float fd[27];
#pragma unroll
    for (int oz = 0; oz < 3; ++oz)
#pragma unroll
        for (int oy = 0; oy < 3; ++oy)
#pragma unroll
            for (int ox = 0; ox < 3; ++ox) {
                int c = oz * 9 + oy * 3 + ox;
                fd[c] = fabsf(s_anat[center + (oz - 1) * HXY + (oy - 1) * HX + (ox - 1)] - ac);
            }

    int   ri[7];
    float rf[14];
#pragma unroll
    for (int k = 0; k < 7;  ++k) ri[k] = 0;
#pragma unroll
    for (int k = 0; k < 14; ++k) rf[k] = 0.0f;

#pragma unroll
    for (int c = 1; c < 27; ++c)
#pragma unroll
        for (int j = 0; j < c; ++j) {
            if (((c + j) & 1) == 0) {
                // int view of non-negative float: identical ordering (ALU pipe)
                if (__float_as_int(fd[j]) <= __float_as_int(fd[c]))
                    ri[c >> 2] += (1 << ((c & 3) * 8));
                else
                    ri[j >> 2] += (1 << ((j & 3) * 8));
            } else {
                // float view (FMA pipe)
                if (fd[j] <= fd[c])
                    rf[c >> 1] += ((c & 1) ? 1024.0f : 1.0f);
                else
                    rf[j >> 1] += ((j & 1) ? 1024.0f : 1.0f);
            }
        }

    int fi[14];
#pragma unroll
    for (int k = 0; k < 14; ++k) fi[k] = (int)rf[k];

    float*         svf = (float*)s_val;
    unsigned char* scb = (unsigned char*)s_code;
#pragma unroll
    for (int c = 0; c < 27; ++c) {
        int r = ((ri[c >> 2] >> ((c & 3) * 8)) & 255)
              + ((c & 1) ? (fi[c >> 1] >> 10) : (fi[c >> 1] & 1023));
        if (r < KNN) {
            int oz = c / 9, rem = c - 9 * oz, oy = rem / 3, ox = rem - 3 * oy; // compile-time
            svf[tid * 12 + r] = s_anat[center + (oz - 1) * HXY + (oy - 1) * HX + (ox - 1)];
            scb[tid * 12 + r] = (unsigned char)c;
        }
    }
    __syncthreads();

    // Coalesced copy-out: 16 (lz,ly) lines x 16 x-contiguous voxels.
    // 48 float4 (and 48 code words) per line.
    for (int q = tid; q < 768; q += 256) {
        int line = q / 48, off = q - line * 48;
        int llz = line >> 2, lly = line & 3;
        int vox = ((z0 + llz) << 14) | ((y0 + lly) << 7) | x0;
        g_val4[vox * 3 + off]   = s_val[q];
        g_code32[vox * 3 + off] = s_code[q];
    }
}

// ---------------------------------------------------------------------------
// Pass 2: load the 648-row g_val halo into smem once (coalesced); every
// neighbor row is then 3 conflict-light LDS.128 at a table-looked-up offset.
// Output staged through smem (stride-9 STS conflict-free) and written
// coalesced. The halo buffer is reused for output staging.
// ---------------------------------------------------------------------------
__global__ __launch_bounds__(256) void pass2_kernel(const float* __restrict__ ksig,
                                                    float* __restrict__ out) {
    __shared__ float4 s_row[HROWS * 3];   // 31104 B, reused for out staging
    __shared__ int    s_tab[27];

    int tid = threadIdx.x;
    int lx = tid & 15, ly = (tid >> 4) & 3, lz = tid >> 6;
    int x0 = blockIdx.x * TX, y0 = blockIdx.y * TY, z0 = blockIdx.z * TZ;

    if (tid < 27) {
        int oz = tid / 9, rem = tid - 9 * oz, oy = rem / 3, ox = rem - 3 * oy;
        s_tab[tid] = (oz - 1) * HXY + (oy - 1) * HX + (ox - 1);
    }

    for (int t = tid; t < HROWS * 3; t += 256) {
        int row = t / 3, comp = t - row * 3;
        int hx = row % HX; int r = row / HX; int hy = r % HY; int hz = r / HY;
        int gx = (x0 + hx + 127) & 127;
        int gy = (y0 + hy + 127) & 127;
        int gz = (z0 + hz + 63) & 63;
        int vox = (gz << 14) | (gy << 7) | gx;
        s_row[t] = g_val4[vox * 3 + comp];
    }

    int i = ((z0 + lz) << 14) | ((y0 + ly) << 7) | (x0 + lx);
    unsigned int cw[3];
    cw[0] = g_code32[i * 3];
    cw[1] = g_code32[i * 3 + 1];
    cw[2] = g_code32[i * 3 + 2];
    float ks = __ldg(&ksig[0]);
    __syncthreads();

    int center = (lz + 1) * HXY + (ly + 1) * HX + (lx + 1);
    float4 a0 = s_row[center * 3], a1 = s_row[center * 3 + 1], a2 = s_row[center * 3 + 2];
    float wi[KNN] = { a0.x, a0.y, a0.z, a0.w, a1.x, a1.y, a1.z, a1.w, a2.x };

    // sigma = std(Wk, ddof=1), two-pass for fp32 stability
    float sum = 0.f;
#pragma unroll
    for (int t = 0; t < KNN; ++t) sum += wi[t];
    float mean = sum * (1.0f / 9.0f);
    float var = 0.f;
#pragma unroll
    for (int t = 0; t < KNN; ++t) { float d = wi[t] - mean; var += d * d; }
    var *= (1.0f / 8.0f);
    float sigma = sqrtf(var);
    bool  zeroSig = (sigma == 0.0f);
    float sig = zeroSig ? 1.0f : sigma;

    // logits = -(||diff|| / sigma / (sqrt(2)*ks))^2 = -s / (2*sigma^2*ks^2)
    float inv = 1.0f / (2.0f * sig * sig * ks * ks);

    float wie[KNN];
#pragma unroll
    for (int t = 0; t < KNN; ++t) wie[t] = wi[t] + 1e-6f;

    float logits[KNN];
#pragma unroll
    for (int j = 0; j < KNN; ++j) {
        int c = (int)((cw[j >> 2] >> ((j & 3) * 8)) & 0xff);
        int rowc = center + s_tab[c];
        float4 b0 = s_row[rowc * 3], b1 = s_row[rowc * 3 + 1], b2 = s_row[rowc * 3 + 2];
        float wn[KNN] = { b0.x, b0.y, b0.z, b0.w, b1.x, b1.y, b1.z, b1.w, b2.x };
        float s = 0.f;
#pragma unroll
        for (int t = 0; t < KNN; ++t) {
            float df = wie[t] - wn[t];
            s = fmaf(df, df, s);
        }
        logits[j] = zeroSig ? 0.0f : -(s * inv);
    }

    // softmax over the 9 neighbors
    float mx = logits[0];
#pragma unroll
    for (int j = 1; j < KNN; ++j) mx = fmaxf(mx, logits[j]);
    float e[KNN], se = 0.f;
#pragma unroll
    for (int j = 0; j < KNN; ++j) { e[j] = __expf(logits[j] - mx); se += e[j]; }
    float rse = 1.0f / se;

    __syncthreads();                       // all halo reads done; reuse buffer
    float* s_outf = (float*)s_row;
#pragma unroll
    for (int j = 0; j < KNN; ++j) s_outf[tid * KNN + j] = e[j] * rse;
    __syncthreads();

    // Coalesced out: 16 lines x (16 voxels * 9 floats = 144 contiguous floats)
    for (int q = tid; q < 2304; q += 256) {
        int line = q / 144, off = q - line * 144;
        int llz = line >> 2, lly = line & 3;
        int vox = ((z0 + llz) << 14) | ((y0 + lly) << 7) | x0;
        out[vox * KNN + off] = s_outf[q];
    }
}

extern "C" void kernel_launch(void* const* d_in, const int* in_sizes, int n_in,
                              void* d_out, int out_size) {
    const float* anat = (const float*)d_in[0];
    const float* ksig = (const float*)d_in[1];
    float* out = (float*)d_out;

    dim3 grid(128 / TX, 128 / TY, 64 / TZ);   // 8 x 32 x 16 = 4096 blocks
    pass1_kernel<<<grid, 256>>>(anat);
    pass2_kernel<<<grid, 256>>>(ksig, out);
}

// round 4
// speedup vs baseline: 1.1864x; 1.0104x over previous
#include <cuda_runtime.h>

// Problem constants: H=64, M=N=128, k=9, w=3
#define PTOT (64 * 128 * 128)
#define KNN  9

// Tile: 16 x 4 x 4 voxels per block; halo 18 x 6 x 6
#define TX 16
#define TY 4
#define TZ 4
#define HX 18
#define HY 6
#define HZH 6
#define HROWS (HX * HY * HZH)   // 648
#define HXY (HX * HY)           // 108

// Scratch: per-voxel 9 selected values (12-float padded row, as 3 float4)
// and 9 window codes (bytes packed in 3 u32 words).
__device__ float4       g_val4[PTOT * 3];    // 50.3 MB
__device__ unsigned int g_code32[PTOT * 3];  // 12.6 MB

// ---------------------------------------------------------------------------
// Pass 1: stable top-9 of 27 periodic window neighbors by |v - center|.
//   rank(c) = #{j<c: d_j <= d_c} + #{j>c: d_j < d_c}
// One compare per unordered pair. Pairs iterated DIAGONALLY (o = c - j outer)
// so consecutive pairs update different accumulator registers (kills the
// accumulator RAW chains). Pipe split by j&1: int compares on the abs-float
// bit pattern (ALU pipe; order-preserving for d >= 0) vs float compares
// (FMA pipe), with matching int-byte / packed-float rank counters.
// ---------------------------------------------------------------------------
__global__ __launch_bounds__(256) void pass1_kernel(const float* __restrict__ anat) {
    __shared__ float        s_anat[HROWS];
    __shared__ float4       s_val[256 * 3];
    __shared__ unsigned int s_code[256 * 3];

    int tid = threadIdx.x;
    int lx = tid & 15, ly = (tid >> 4) & 3, lz = tid >> 6;
    int x0 = blockIdx.x * TX, y0 = blockIdx.y * TY, z0 = blockIdx.z * TZ;

    for (int t = tid; t < HROWS; t += 256) {
        int hx = t % HX; int r = t / HX; int hy = r % HY; int hz = r / HY;
        int gx = (x0 + hx + 127) & 127;
        int gy = (y0 + hy + 127) & 127;
        int gz = (z0 + hz + 63) & 63;
        s_anat[t] = __ldg(&anat[(gz << 14) | (gy << 7) | gx]);
    }
    __syncthreads();

    int center = (lz + 1) * HXY + (ly + 1) * HX + (lx + 1);
    float ac = s_anat[center];

    float fd[27];
#pragma unroll
    for (int oz = 0; oz < 3; ++oz)
#pragma unroll
        for (int oy = 0; oy < 3; ++oy)
#pragma unroll
            for (int ox = 0; ox < 3; ++ox) {
                int c = oz * 9 + oy * 3 + ox;
                fd[c] = fabsf(s_anat[center + (oz - 1) * HXY + (oy - 1) * HX + (ox - 1)] - ac);
            }

    int   ri[7];
    float rf[14];
#pragma unroll
    for (int k = 0; k < 7;  ++k) ri[k] = 0;
#pragma unroll
    for (int k = 0; k < 14; ++k) rf[k] = 0.0f;

    // Diagonal iteration: pair (j, c=j+o). Accumulators rotate each step.
#pragma unroll
    for (int o = 1; o < 27; ++o)
#pragma unroll
        for (int j = 0; j + o < 27; ++j) {
            const int c = j + o;
            if (j & 1) {
                // int view of non-negative float: identical ordering (ALU pipe)
                if (__float_as_int(fd[j]) <= __float_as_int(fd[c]))
                    ri[c >> 2] += (1 << ((c & 3) * 8));
                else
                    ri[j >> 2] += (1 << ((j & 3) * 8));
            } else {
                // float compare (FMA pipe)
                if (fd[j] <= fd[c])
                    rf[c >> 1] += ((c & 1) ? 1024.0f : 1.0f);
                else
                    rf[j >> 1] += ((j & 1) ? 1024.0f : 1.0f);
            }
        }

    int fi[14];
#pragma unroll
    for (int k = 0; k < 14; ++k) fi[k] = (int)rf[k];

    float*         svf = (float*)s_val;
    unsigned char* scb = (unsigned char*)s_code;
#pragma unroll
    for (int c = 0; c < 27; ++c) {
        int r = ((ri[c >> 2] >> ((c & 3) * 8)) & 255)
              + ((c & 1) ? (fi[c >> 1] >> 10) : (fi[c >> 1] & 1023));
        if (r < KNN) {
            int oz = c / 9, rem = c - 9 * oz, oy = rem / 3, ox = rem - 3 * oy; // compile-time
            svf[tid * 12 + r] = s_anat[center + (oz - 1) * HXY + (oy - 1) * HX + (ox - 1)];
            scb[tid * 12 + r] = (unsigned char)c;
        }
    }
    __syncthreads();

    // Coalesced copy-out: 16 (lz,ly) lines x 48 float4 per line.
    for (int q = tid; q < 768; q += 256) {
        int line = q / 48, off = q - line * 48;
        int llz = line >> 2, lly = line & 3;
        int vox = ((z0 + llz) << 14) | ((y0 + lly) << 7) | x0;
        g_val4[vox * 3 + off]   = s_val[q];
        g_code32[vox * 3 + off] = s_code[q];
    }
}

// ---------------------------------------------------------------------------
// Pass 2: load the 648-row g_val halo into smem once (coalesced); every
// neighbor row is then 3 conflict-free LDS.128 at a table-looked-up offset.
// Output staged through smem, written back as float4 (coalesced).
// ---------------------------------------------------------------------------
__global__ __launch_bounds__(256) void pass2_kernel(const float* __restrict__ ksig,
                                                    float* __restrict__ out) {
    __shared__ float4 s_row[HROWS * 3];   // 31104 B, reused for out staging
    __shared__ int    s_tab[27];

    int tid = threadIdx.x;
    int lx = tid & 15, ly = (tid >> 4) & 3, lz = tid >> 6;
    int x0 = blockIdx.x * TX, y0 = blockIdx.y * TY, z0 = blockIdx.z * TZ;

    if (tid < 27) {
        int oz = tid / 9, rem = tid - 9 * oz, oy = rem / 3, ox = rem - 3 * oy;
        s_tab[tid] = (oz - 1) * HXY + (oy - 1) * HX + (ox - 1);
    }

    for (int t = tid; t < HROWS * 3; t += 256) {
        int row = t / 3, comp = t - row * 3;
        int hx = row % HX; int r = row / HX; int hy = r % HY; int hz = r / HY;
        int gx = (x0 + hx + 127) & 127;
        int gy = (y0 + hy + 127) & 127;
        int gz = (z0 + hz + 63) & 63;
        int vox = (gz << 14) | (gy << 7) | gx;
        s_row[t] = g_val4[vox * 3 + comp];
    }

    int i = ((z0 + lz) << 14) | ((y0 + ly) << 7) | (x0 + lx);
    unsigned int cw[3];
    cw[0] = g_code32[i * 3];
    cw[1] = g_code32[i * 3 + 1];
    cw[2] = g_code32[i * 3 + 2];
    float ks = __ldg(&ksig[0]);
    __syncthreads();

    int center = (lz + 1) * HXY + (ly + 1) * HX + (lx + 1);
    float4 a0 = s_row[center * 3], a1 = s_row[center * 3 + 1], a2 = s_row[center * 3 + 2];
    float wi[KNN] = { a0.x, a0.y, a0.z, a0.w, a1.x, a1.y, a1.z, a1.w, a2.x };

    // sigma = std(Wk, ddof=1), two-pass for fp32 stability
    float sum = 0.f;
#pragma unroll
    for (int t = 0; t < KNN; ++t) sum += wi[t];
    float mean = sum * (1.0f / 9.0f);
    float var = 0.f;
#pragma unroll
    for (int t = 0; t < KNN; ++t) { float d = wi[t] - mean; var += d * d; }
    var *= (1.0f / 8.0f);
    float sigma = sqrtf(var);
    bool  zeroSig = (sigma == 0.0f);
    float sig = zeroSig ? 1.0f : sigma;

    // logits = -(||diff|| / sigma / (sqrt(2)*ks))^2 = -s / (2*sigma^2*ks^2)
    float inv = 1.0f / (2.0f * sig * sig * ks * ks);

    float wie[KNN];
#pragma unroll
    for (int t = 0; t < KNN; ++t) wie[t] = wi[t] + 1e-6f;

    float logits[KNN];
#pragma unroll
    for (int j = 0; j < KNN; ++j) {
        int c = (int)((cw[j >> 2] >> ((j & 3) * 8)) & 0xff);
        int rowc = center + s_tab[c];
        float4 b0 = s_row[rowc * 3], b1 = s_row[rowc * 3 + 1], b2 = s_row[rowc * 3 + 2];
        float wn[KNN] = { b0.x, b0.y, b0.z, b0.w, b1.x, b1.y, b1.z, b1.w, b2.x };
        float s = 0.f;
#pragma unroll
        for (int t = 0; t < KNN; ++t) {
            float df = wie[t] - wn[t];
            s = fmaf(df, df, s);
        }
        logits[j] = zeroSig ? 0.0f : -(s * inv);
    }

    // softmax over the 9 neighbors
    float mx = logits[0];
#pragma unroll
    for (int j = 1; j < KNN; ++j) mx = fmaxf(mx, logits[j]);
    float e[KNN], se = 0.f;
#pragma unroll
    for (int j = 0; j < KNN; ++j) { e[j] = __expf(logits[j] - mx); se += e[j]; }
    float rse = 1.0f / se;

    __syncthreads();                       // all halo reads done; reuse buffer
    float* s_outf = (float*)s_row;
#pragma unroll
    for (int j = 0; j < KNN; ++j) s_outf[tid * KNN + j] = e[j] * rse;
    __syncthreads();

    // Coalesced out: 16 lines x 144 floats = 36 float4 per line, 576 total.
    // Block base offset in floats: vox*9 with x0 multiple of 16 -> 16B aligned.
    float4* s_out4 = (float4*)s_row;
    for (int q = tid; q < 576; q += 256) {
        int line = q / 36, off = q - line * 36;
        int llz = line >> 2, lly = line & 3;
        int vox = ((z0 + llz) << 14) | ((y0 + lly) << 7) | x0;
        ((float4*)(out + (size_t)vox * KNN))[off] = s_out4[q];
    }
}

extern "C" void kernel_launch(void* const* d_in, const int* in_sizes, int n_in,
                              void* d_out, int out_size) {
    const float* anat = (const float*)d_in[0];
    const float* ksig = (const float*)d_in[1];
    float* out = (float*)d_out;

    dim3 grid(128 / TX, 128 / TY, 64 / TZ);   // 8 x 32 x 16 = 4096 blocks
    pass1_kernel<<<grid, 256>>>(anat);
    pass2_kernel<<<grid, 256>>>(ksig, out);
}